// round 15
// baseline (speedup 1.0000x reference)
#include <cuda_runtime.h>
#include <cuda_bf16.h>
#include <mma.h>
#include <cstdint>

using namespace nvcuda;

#define Nn 50000
#define Ee 800000
#define Dd 128
#define Hh 256
#define Tt 10000
#define EPSV 1e-5f
#define SCAN_BLOCKS 196
#define NPAD 50048   // 391 * 128

// ---------------- scratch ----------------
__device__ float g_disqrt[Nn];
__device__ int   g_cnt[Nn];
__device__ int   g_off[Nn + 1];
__device__ int   g_cursor[Nn];
__device__ unsigned long long g_lb[SCAN_BLOCKS];   // lookback: flag<<32 | value
__device__ int2  g_edge[Ee];                        // packed {src, norm-bits}
__device__ float g_hw[(size_t)NPAD * Hh];
__device__ float g_stats4[4][2 * Hh];
__device__ __nv_bfloat16 g_ahi[(size_t)Nn * Hh];
__device__ __nv_bfloat16 g_alo[(size_t)Nn * Hh];
__device__ __nv_bfloat16 g_ghi[(size_t)Tt * Hh];
__device__ __nv_bfloat16 g_glo[(size_t)Tt * Hh];
__device__ __nv_bfloat16 g_whi[4 * Hh * Hh];
__device__ __nv_bfloat16 g_wlo[4 * Hh * Hh];

// ---------------- helpers ----------------
__device__ __forceinline__ void cp16(uint32_t dst, const void* src, int bytes) {
    asm volatile("cp.async.cg.shared.global [%0], [%1], 16, %2;"
                 :: "r"(dst), "l"(src), "r"(bytes) : "memory");
}
#define CP_COMMIT() asm volatile("cp.async.commit_group;" ::: "memory")
#define CP_WAIT1()  asm volatile("cp.async.wait_group 1;" ::: "memory")
#define CP_WAIT0()  asm volatile("cp.async.wait_group 0;" ::: "memory")

// ---------------- graph preprocessing ----------------
__global__ void k_zero_init() {
    int i = blockIdx.x * blockDim.x + threadIdx.x;
    if (i < Nn) g_cnt[i] = 0;
    if (i < 4 * 2 * Hh) ((float*)g_stats4)[i] = 0.0f;
    if (i < SCAN_BLOCKS) g_lb[i] = 0ULL;
}
__global__ void k_count(const int* __restrict__ row) {
    int e = blockIdx.x * blockDim.x + threadIdx.x;
    if (e < Ee) atomicAdd(&g_cnt[row[e]], 1);
}

// single-pass decoupled-lookback scan (+disqrt, +cursor init)
__global__ void k_scan_lb() {
    int t = threadIdx.x, b = blockIdx.x;
    int i = b * 256 + t;
    int v = (i < Nn) ? g_cnt[i] : 0;
    if (i < Nn) g_disqrt[i] = rsqrtf((float)v + 1.0f);

    int lane = t & 31, w = t >> 5;
    int x = v;
#pragma unroll
    for (int o = 1; o < 32; o <<= 1) {
        int y = __shfl_up_sync(0xffffffffu, x, o);
        if (lane >= o) x += y;
    }
    __shared__ int wsum[8];
    if (lane == 31) wsum[w] = x;
    __syncthreads();
    if (w == 0) {
        int s = (lane < 8) ? wsum[lane] : 0;
#pragma unroll
        for (int o = 1; o < 8; o <<= 1) {
            int y = __shfl_up_sync(0xffffffffu, s, o);
            if (lane >= o) s += y;
        }
        if (lane < 8) wsum[lane] = s;
    }
    __syncthreads();
    int incl = x + (w > 0 ? wsum[w - 1] : 0);   // block-local inclusive

    __shared__ int blockAgg, blockPrefix;
    if (t == 255) blockAgg = incl;
    __syncthreads();

    if (t == 0) {
        int agg = blockAgg;
        if (b == 0) {
            __threadfence();
            atomicExch(&g_lb[0], (2ULL << 32) | (unsigned)agg);
            blockPrefix = 0;
        } else {
            __threadfence();
            atomicExch(&g_lb[b], (1ULL << 32) | (unsigned)agg);
            int run = 0;
            for (int p = b - 1; p >= 0; p--) {
                unsigned long long pk;
                do { pk = atomicAdd(&g_lb[p], 0ULL); } while ((pk >> 32) == 0ULL);
                run += (int)(unsigned)pk;
                if ((pk >> 32) == 2ULL) break;
            }
            __threadfence();
            atomicExch(&g_lb[b], (2ULL << 32) | (unsigned)(run + agg));
            blockPrefix = run;
        }
    }
    __syncthreads();

    int excl = blockPrefix + incl - v;
    if (i < Nn) {
        g_off[i] = excl;
        g_cursor[i] = excl;
    }
    if (i == 0) g_off[Nn] = Ee;
}

__global__ void k_scatter(const int* __restrict__ row, const int* __restrict__ col) {
    int e = blockIdx.x * blockDim.x + threadIdx.x;
    if (e < Ee) {
        int d = row[e];
        int s = col[e];
        int pos = atomicAdd(&g_cursor[d], 1);
        float nm = g_disqrt[d] * g_disqrt[s];
        g_edge[pos] = make_int2(s, __float_as_int(nm));
    }
}

// ---------------- all-weights bf16 split ----------------
__global__ void k_wsplit_all(const float* __restrict__ W1, const float* __restrict__ W2,
                             const float* __restrict__ W3, const float* __restrict__ Wl) {
    int idx = blockIdx.x * blockDim.x + threadIdx.x;
    const int S1 = Dd * Hh;
    const int SW = Hh * Hh;
    const int total = S1 + 3 * SW;
    if (idx >= total) return;
    const float* src;
    int dofs;
    if (idx < S1) { src = W1 + idx; dofs = idx; }
    else {
        int r = idx - S1;
        int which = r / SW, o = r % SW;
        src = (which == 0 ? W2 : which == 1 ? W3 : Wl) + o;
        dofs = (which + 1) * SW + o;
    }
    float v = *src;
    __nv_bfloat16 h = __float2bfloat16_rn(v);
    g_whi[dofs] = h;
    g_wlo[dofs] = __float2bfloat16_rn(v - __bfloat162float(h));
}

// ---------------- aggregation (warp/node, fused BN+ReLU, unroll-4 edges) ----------------
template <int KC, bool BN>
__global__ void k_agg(const float* __restrict__ src,
                      const float* __restrict__ stats_in,
                      const float* __restrict__ gamma, const float* __restrict__ beta,
                      __nv_bfloat16* __restrict__ dhi, __nv_bfloat16* __restrict__ dlo) {
    constexpr int Q = KC / 128;
    int wid = threadIdx.x >> 5, lane = threadIdx.x & 31;
    int node = blockIdx.x * 8 + wid;
    if (node >= Nn) return;

    float scale[Q][4], shift[Q][4];
    if (BN) {
        const float invN = 1.0f / (float)Nn;
#pragma unroll
        for (int q = 0; q < Q; q++)
#pragma unroll
            for (int k = 0; k < 4; k++) {
                int j = q * 128 + lane * 4 + k;
                float mu = stats_in[j] * invN;
                float var = fmaxf(stats_in[Hh + j] * invN - mu * mu, 0.0f);
                float sc = gamma[j] * rsqrtf(var + EPSV);
                scale[q][k] = sc;
                shift[q][k] = beta[j] - mu * sc;
            }
    }

    const float4* s4 = (const float4*)src;
    float dsq = g_disqrt[node];
    float sl = dsq * dsq;

    float acc[Q][4];
#pragma unroll
    for (int q = 0; q < Q; q++) {
        float4 v = s4[(size_t)node * (Q * 32) + q * 32 + lane];
        float t[4] = {v.x, v.y, v.z, v.w};
#pragma unroll
        for (int k = 0; k < 4; k++) {
            float u = BN ? fmaxf(fmaf(t[k], scale[q][k], shift[q][k]), 0.0f) : t[k];
            acc[q][k] = u * sl;
        }
    }

    int e0 = g_off[node], e1 = g_off[node + 1];
    int e = e0;
    // unroll-4: four edges' gather loads issue before their FMAs
    for (; e + 4 <= e1; e += 4) {
        int2 ed0 = g_edge[e];
        int2 ed1 = g_edge[e + 1];
        int2 ed2 = g_edge[e + 2];
        int2 ed3 = g_edge[e + 3];
        float nm0 = __int_as_float(ed0.y);
        float nm1 = __int_as_float(ed1.y);
        float nm2 = __int_as_float(ed2.y);
        float nm3 = __int_as_float(ed3.y);
        float4 v0[Q], v1[Q], v2[Q], v3[Q];
#pragma unroll
        for (int q = 0; q < Q; q++) {
            v0[q] = s4[(size_t)ed0.x * (Q * 32) + q * 32 + lane];
            v1[q] = s4[(size_t)ed1.x * (Q * 32) + q * 32 + lane];
            v2[q] = s4[(size_t)ed2.x * (Q * 32) + q * 32 + lane];
            v3[q] = s4[(size_t)ed3.x * (Q * 32) + q * 32 + lane];
        }
#pragma unroll
        for (int q = 0; q < Q; q++) {
            float t0[4] = {v0[q].x, v0[q].y, v0[q].z, v0[q].w};
            float t1[4] = {v1[q].x, v1[q].y, v1[q].z, v1[q].w};
            float t2[4] = {v2[q].x, v2[q].y, v2[q].z, v2[q].w};
            float t3[4] = {v3[q].x, v3[q].y, v3[q].z, v3[q].w};
#pragma unroll
            for (int k = 0; k < 4; k++) {
                float u0 = BN ? fmaxf(fmaf(t0[k], scale[q][k], shift[q][k]), 0.0f) : t0[k];
                acc[q][k] = fmaf(u0, nm0, acc[q][k]);
                float u1 = BN ? fmaxf(fmaf(t1[k], scale[q][k], shift[q][k]), 0.0f) : t1[k];
                acc[q][k] = fmaf(u1, nm1, acc[q][k]);
                float u2 = BN ? fmaxf(fmaf(t2[k], scale[q][k], shift[q][k]), 0.0f) : t2[k];
                acc[q][k] = fmaf(u2, nm2, acc[q][k]);
                float u3 = BN ? fmaxf(fmaf(t3[k], scale[q][k], shift[q][k]), 0.0f) : t3[k];
                acc[q][k] = fmaf(u3, nm3, acc[q][k]);
            }
        }
    }
    for (; e < e1; e++) {
        int2 ed = g_edge[e];
        float nm = __int_as_float(ed.y);
#pragma unroll
        for (int q = 0; q < Q; q++) {
            float4 v = s4[(size_t)ed.x * (Q * 32) + q * 32 + lane];
            float t[4] = {v.x, v.y, v.z, v.w};
#pragma unroll
            for (int k = 0; k < 4; k++) {
                float u = BN ? fmaxf(fmaf(t[k], scale[q][k], shift[q][k]), 0.0f) : t[k];
                acc[q][k] = fmaf(u, nm, acc[q][k]);
            }
        }
    }

#pragma unroll
    for (int q = 0; q < Q; q++) {
        size_t bb = (size_t)node * KC + q * 128 + lane * 4;
        float h[4], l[4];
#pragma unroll
        for (int k = 0; k < 4; k++) {
            __nv_bfloat16 hb = __float2bfloat16_rn(acc[q][k]);
            h[k] = __bfloat162float(hb);
            l[k] = acc[q][k] - h[k];
        }
        *(__nv_bfloat162*)(dhi + bb) = __floats2bfloat162_rn(h[0], h[1]);
        *(__nv_bfloat162*)(dhi + bb + 2) = __floats2bfloat162_rn(h[2], h[3]);
        *(__nv_bfloat162*)(dlo + bb) = __floats2bfloat162_rn(l[0], l[1]);
        *(__nv_bfloat162*)(dlo + bb + 2) = __floats2bfloat162_rn(l[2], l[3]);
    }
}

// ---------------- 3xBF16 wmma GEMM, 2-stage cp.async, fused stats ----------------
#define GBK 32
#define ALD 40
#define BLD 136
#define CLD 132
#define STAGE_BYTES ((2 * 128 * ALD * 2 + 2 * GBK * BLD * 2) * 2)  // 75776
#define CTILE_BYTES (128 * CLD * 4)                                 // 67584
#define SMEM_GEMM (STAGE_BYTES > CTILE_BYTES ? STAGE_BYTES : CTILE_BYTES)

using AFrag = wmma::fragment<wmma::matrix_a, 16, 16, 16, __nv_bfloat16, wmma::row_major>;
using BFrag = wmma::fragment<wmma::matrix_b, 16, 16, 16, __nv_bfloat16, wmma::row_major>;
using CFrag = wmma::fragment<wmma::accumulator, 16, 16, 16, float>;

__global__ __launch_bounds__(256) void k_gemm(const __nv_bfloat16* __restrict__ Ahi,
                                              const __nv_bfloat16* __restrict__ Alo,
                                              const __nv_bfloat16* __restrict__ Bhi,
                                              const __nv_bfloat16* __restrict__ Blo,
                                              float* __restrict__ C,
                                              float* __restrict__ stats,
                                              int M, int K) {
    extern __shared__ __nv_bfloat16 sm[];
    __nv_bfloat16* AH = sm;
    __nv_bfloat16* AL = AH + 2 * 128 * ALD;
    __nv_bfloat16* BH = AL + 2 * 128 * ALD;
    __nv_bfloat16* BL = BH + 2 * GBK * BLD;

    const int tid = threadIdx.x;
    const int warp = tid >> 5;
    const int rowBase = blockIdx.y * 128;
    const int colBase = blockIdx.x * 128;
    const int wm = warp & 3;
    const int wn = warp >> 2;

    CFrag c[2][4];
#pragma unroll
    for (int i = 0; i < 2; i++)
#pragma unroll
        for (int j = 0; j < 4; j++) wmma::fill_fragment(c[i][j], 0.0f);

    auto load_stage = [&](int buf, int k0) {
#pragma unroll
        for (int t = 0; t < 2; t++) {
            int id = tid + t * 256;
            int r = id >> 2;
            int cc = (id & 3) * 8;
            int grow = rowBase + r;
            size_t gofs = (size_t)(grow < M ? grow : 0) * K + k0 + cc;
            int bytes = grow < M ? 16 : 0;
            cp16((uint32_t)__cvta_generic_to_shared(AH + ((size_t)buf * 128 + r) * ALD + cc),
                 Ahi + gofs, bytes);
            cp16((uint32_t)__cvta_generic_to_shared(AL + ((size_t)buf * 128 + r) * ALD + cc),
                 Alo + gofs, bytes);
        }
#pragma unroll
        for (int t = 0; t < 2; t++) {
            int id = tid + t * 256;
            int kr = id >> 4;
            int nc = (id & 15) * 8;
            size_t gofs = (size_t)(k0 + kr) * Hh + colBase + nc;
            cp16((uint32_t)__cvta_generic_to_shared(BH + ((size_t)buf * GBK + kr) * BLD + nc),
                 Bhi + gofs, 16);
            cp16((uint32_t)__cvta_generic_to_shared(BL + ((size_t)buf * GBK + kr) * BLD + nc),
                 Blo + gofs, 16);
        }
    };

    const int NC = K >> 5;
    load_stage(0, 0);
    CP_COMMIT();

    for (int cidx = 0; cidx < NC; cidx++) {
        int buf = cidx & 1;
        if (cidx + 1 < NC) {
            load_stage(buf ^ 1, (cidx + 1) << 5);
            CP_COMMIT();
            CP_WAIT1();
        } else {
            CP_WAIT0();
        }
        __syncthreads();

#pragma unroll
        for (int ks = 0; ks < 2; ks++) {
            AFrag ah[2], al[2];
            BFrag bh[4], bl[4];
#pragma unroll
            for (int i = 0; i < 2; i++) {
                const __nv_bfloat16* pa = AH + ((size_t)buf * 128 + wm * 32 + i * 16) * ALD + ks * 16;
                wmma::load_matrix_sync(ah[i], pa, ALD);
                wmma::load_matrix_sync(al[i], pa + 2 * 128 * ALD, ALD);
            }
#pragma unroll
            for (int j = 0; j < 4; j++) {
                const __nv_bfloat16* pb = BH + ((size_t)buf * GBK + ks * 16) * BLD + wn * 64 + j * 16;
                wmma::load_matrix_sync(bh[j], pb, BLD);
                wmma::load_matrix_sync(bl[j], pb + 2 * GBK * BLD, BLD);
            }
#pragma unroll
            for (int i = 0; i < 2; i++)
#pragma unroll
                for (int j = 0; j < 4; j++) {
                    wmma::mma_sync(c[i][j], ah[i], bh[j], c[i][j]);
                    wmma::mma_sync(c[i][j], ah[i], bl[j], c[i][j]);
                    wmma::mma_sync(c[i][j], al[i], bh[j], c[i][j]);
                }
        }
        __syncthreads();
    }

    // store to gmem
#pragma unroll
    for (int i = 0; i < 2; i++)
#pragma unroll
        for (int j = 0; j < 4; j++) {
            int grow = rowBase + wm * 32 + i * 16;
            wmma::store_matrix_sync(C + (size_t)grow * Hh + colBase + wn * 64 + j * 16,
                                    c[i][j], Hh, wmma::mem_row_major);
        }

    // fused BN stats (barrier first: mainloop smem reads must retire before overwrite)
    if (stats) {
        __syncthreads();
        float* ct = (float*)sm;
#pragma unroll
        for (int i = 0; i < 2; i++)
#pragma unroll
            for (int j = 0; j < 4; j++)
                wmma::store_matrix_sync(ct + (size_t)(wm * 32 + i * 16) * CLD + wn * 64 + j * 16,
                                        c[i][j], CLD, wmma::mem_row_major);
        __syncthreads();
        int col = tid & 127;
        int half = tid >> 7;
        const float* p = ct + (size_t)half * 64 * CLD + col;
        float s = 0.f, s2 = 0.f;
#pragma unroll 8
        for (int r = 0; r < 64; r++) {
            float v = p[(size_t)r * CLD];
            s += v;
            s2 = fmaf(v, v, s2);
        }
        atomicAdd(&stats[colBase + col], s);
        atomicAdd(&stats[Hh + colBase + col], s2);
    }
}

// ---------------- head: gather + BN3 + relu + bf16 split ----------------
__global__ void k_gather_bn(const int* __restrict__ train, const float* __restrict__ stats,
                            const float* __restrict__ gamma, const float* __restrict__ beta) {
    int idx = blockIdx.x * blockDim.x + threadIdx.x;
    if (idx >= Tt * 64) return;
    int t = idx >> 6, cq = idx & 63;
    int node = train[t];
    float4 v = ((const float4*)g_hw)[(size_t)node * 64 + cq];
    const float invN = 1.0f / (float)Nn;
    float tv[4] = {v.x, v.y, v.z, v.w};
    float h[4], l[4];
#pragma unroll
    for (int k = 0; k < 4; k++) {
        int j = cq * 4 + k;
        float mu = stats[j] * invN;
        float var = fmaxf(stats[Hh + j] * invN - mu * mu, 0.0f);
        float sc = gamma[j] * rsqrtf(var + EPSV);
        float u = fmaxf(fmaf(tv[k], sc, beta[j] - mu * sc), 0.0f);
        __nv_bfloat16 hb = __float2bfloat16_rn(u);
        h[k] = __bfloat162float(hb);
        l[k] = u - h[k];
    }
    size_t base = (size_t)t * Hh + cq * 4;
    *(__nv_bfloat162*)(g_ghi + base) = __floats2bfloat162_rn(h[0], h[1]);
    *(__nv_bfloat162*)(g_ghi + base + 2) = __floats2bfloat162_rn(h[2], h[3]);
    *(__nv_bfloat162*)(g_glo + base) = __floats2bfloat162_rn(l[0], l[1]);
    *(__nv_bfloat162*)(g_glo + base + 2) = __floats2bfloat162_rn(l[2], l[3]);
}

__global__ void k_out(const float* __restrict__ bl, const float* __restrict__ Wf,
                      const float* __restrict__ bf, float* __restrict__ out) {
    int warp = (blockIdx.x * blockDim.x + threadIdx.x) >> 5;
    int lane = threadIdx.x & 31;
    if (warp >= Tt) return;
    float acc = 0.f;
    const float* hp = g_hw + (size_t)warp * Hh;
#pragma unroll
    for (int j0 = 0; j0 < Hh; j0 += 32) {
        int j = j0 + lane;
        float v = fmaxf(hp[j] + bl[j], 0.0f);
        acc = fmaf(v, Wf[j], acc);
    }
#pragma unroll
    for (int o = 16; o > 0; o >>= 1) acc += __shfl_xor_sync(0xffffffffu, acc, o);
    if (lane == 0) out[warp] = acc + bf[0];
}

// ---------------- launch ----------------
extern "C" void kernel_launch(void* const* d_in, const int* in_sizes, int n_in,
                              void* d_out, int out_size) {
    const float* x = (const float*)d_in[0];
    const int* ei = (const int*)d_in[1];
    const int* train = (const int*)d_in[2];
    const float* W1 = (const float*)d_in[3];
    const float* W2 = (const float*)d_in[5];
    const float* W3 = (const float*)d_in[7];
    const float* g1 = (const float*)d_in[9];
    const float* be1 = (const float*)d_in[10];
    const float* g2 = (const float*)d_in[11];
    const float* be2 = (const float*)d_in[12];
    const float* g3 = (const float*)d_in[13];
    const float* be3 = (const float*)d_in[14];
    const float* Wl = (const float*)d_in[15];
    const float* bl = (const float*)d_in[16];
    const float* Wf = (const float*)d_in[17];
    const float* bf = (const float*)d_in[18];
    float* out = (float*)d_out;

    const int* row = ei;
    const int* col = ei + Ee;

    float *p_hw, *p_stats;
    __nv_bfloat16 *p_ahi, *p_alo, *p_ghi, *p_glo, *p_whi, *p_wlo;
    cudaGetSymbolAddress((void**)&p_hw, g_hw);
    cudaGetSymbolAddress((void**)&p_stats, g_stats4);
    cudaGetSymbolAddress((void**)&p_ahi, g_ahi);
    cudaGetSymbolAddress((void**)&p_alo, g_alo);
    cudaGetSymbolAddress((void**)&p_ghi, g_ghi);
    cudaGetSymbolAddress((void**)&p_glo, g_glo);
    cudaGetSymbolAddress((void**)&p_whi, g_whi);
    cudaGetSymbolAddress((void**)&p_wlo, g_wlo);

    cudaFuncSetAttribute(k_gemm, cudaFuncAttributeMaxDynamicSharedMemorySize, SMEM_GEMM);

    // ---- graph preprocessing ----
    k_zero_init<<<(Nn + 255) / 256, 256>>>();
    k_count<<<(Ee + 255) / 256, 256>>>(row);
    k_scan_lb<<<SCAN_BLOCKS, 256>>>();
    k_scatter<<<(Ee + 255) / 256, 256>>>(row, col);
    k_wsplit_all<<<(Dd * Hh + 3 * Hh * Hh + 255) / 256, 256>>>(W1, W2, W3, Wl);

    const int AGG_B = (Nn + 7) / 8;   // 6250
    dim3 gemm_grid(2, NPAD / 128);
    dim3 head_grid(2, (Tt + 127) / 128);
    float* st0 = p_stats + 0 * 2 * Hh;
    float* st1 = p_stats + 1 * 2 * Hh;
    float* st2 = p_stats + 2 * 2 * Hh;

    // ---- layer 1: agg(x) -> bf16; GEMM K=128 ----
    k_agg<128, false><<<AGG_B, 256>>>(x, nullptr, nullptr, nullptr, p_ahi, p_alo);
    k_gemm<<<gemm_grid, 256, SMEM_GEMM>>>(p_ahi, p_alo, p_whi, p_wlo, p_hw, st0, Nn, Dd);

    // ---- layer 2 ----
    k_agg<256, true><<<AGG_B, 256>>>(p_hw, st0, g1, be1, p_ahi, p_alo);
    k_gemm<<<gemm_grid, 256, SMEM_GEMM>>>(p_ahi, p_alo, p_whi + 1 * Hh * Hh,
                                          p_wlo + 1 * Hh * Hh, p_hw, st1, Nn, Hh);

    // ---- layer 3 ----
    k_agg<256, true><<<AGG_B, 256>>>(p_hw, st1, g2, be2, p_ahi, p_alo);
    k_gemm<<<gemm_grid, 256, SMEM_GEMM>>>(p_ahi, p_alo, p_whi + 2 * Hh * Hh,
                                          p_wlo + 2 * Hh * Hh, p_hw, st2, Nn, Hh);

    // ---- head: gather+bn3 -> bf16; Wl GEMM; fused relu+Wf dot ----
    k_gather_bn<<<(Tt * 64 + 255) / 256, 256>>>(train, st2, g3, be3);
    k_gemm<<<head_grid, 256, SMEM_GEMM>>>(p_ghi, p_glo, p_whi + 3 * Hh * Hh,
                                          p_wlo + 3 * Hh * Hh, p_hw, nullptr, Tt, Hh);
    k_out<<<(Tt * 32 + 255) / 256, 256>>>(bl, Wf, bf, out);
}

// round 16
// speedup vs baseline: 1.1154x; 1.1154x over previous
#include <cuda_runtime.h>
#include <cuda_bf16.h>
#include <cuda_fp16.h>
#include <mma.h>
#include <cstdint>

using namespace nvcuda;

#define Nn 50000
#define Ee 800000
#define Dd 128
#define Hh 256
#define Tt 10000
#define EPSV 1e-5f
#define SCAN_BLOCKS 196
#define NPAD 50048   // 391 * 128
#define TPAD 10112   // 79 * 128

// ---------------- scratch ----------------
__device__ float g_disqrt[Nn];
__device__ int   g_cnt[Nn];
__device__ int   g_off[Nn + 1];
__device__ int   g_cursor[Nn];
__device__ int   g_bsum[SCAN_BLOCKS];
__device__ int2  g_edge[Ee];                       // packed {src, norm-bits}
__device__ __half g_hw[(size_t)NPAD * Hh];         // activations (fp16 transport)
__device__ float  g_ho[(size_t)TPAD * Hh];         // head GEMM output (fp32)
__device__ float g_stats4[4][2 * Hh];              // per-layer [sum|sumsq] (exact fp32)
__device__ __nv_bfloat16 g_ahi[(size_t)Nn * Hh];
__device__ __nv_bfloat16 g_alo[(size_t)Nn * Hh];
__device__ __nv_bfloat16 g_ghi[(size_t)Tt * Hh];
__device__ __nv_bfloat16 g_glo[(size_t)Tt * Hh];
__device__ __nv_bfloat16 g_whi[4 * Hh * Hh];
__device__ __nv_bfloat16 g_wlo[4 * Hh * Hh];

// ---------------- helpers ----------------
__device__ __forceinline__ void cp16(uint32_t dst, const void* src, int bytes) {
    asm volatile("cp.async.cg.shared.global [%0], [%1], 16, %2;"
                 :: "r"(dst), "l"(src), "r"(bytes) : "memory");
}
#define CP_COMMIT() asm volatile("cp.async.commit_group;" ::: "memory")
#define CP_WAIT1()  asm volatile("cp.async.wait_group 1;" ::: "memory")
#define CP_WAIT0()  asm volatile("cp.async.wait_group 0;" ::: "memory")

// ---------------- graph preprocessing ----------------
__global__ void k_zero_init() {
    int i = blockIdx.x * blockDim.x + threadIdx.x;
    if (i < Nn) g_cnt[i] = 0;
    if (i < 4 * 2 * Hh) ((float*)g_stats4)[i] = 0.0f;
}
__global__ void k_count(const int* __restrict__ row) {
    int e = blockIdx.x * blockDim.x + threadIdx.x;
    if (e < Ee) atomicAdd(&g_cnt[row[e]], 1);
}
__global__ void k_scan1() {
    int t = threadIdx.x, b = blockIdx.x;
    int i = b * 256 + t;
    int v = (i < Nn) ? g_cnt[i] : 0;
    if (i < Nn) g_disqrt[i] = rsqrtf((float)v + 1.0f);
    int lane = t & 31, w = t >> 5;
    int x = v;
#pragma unroll
    for (int o = 1; o < 32; o <<= 1) {
        int y = __shfl_up_sync(0xffffffffu, x, o);
        if (lane >= o) x += y;
    }
    __shared__ int wsum[8];
    if (lane == 31) wsum[w] = x;
    __syncthreads();
    if (w == 0) {
        int s = (lane < 8) ? wsum[lane] : 0;
#pragma unroll
        for (int o = 1; o < 8; o <<= 1) {
            int y = __shfl_up_sync(0xffffffffu, s, o);
            if (lane >= o) s += y;
        }
        if (lane < 8) wsum[lane] = s;
    }
    __syncthreads();
    int incl = x + (w > 0 ? wsum[w - 1] : 0);
    if (i < Nn) g_off[i] = incl - v;
    if (t == 255) g_bsum[b] = incl;
}
__global__ void k_scan2() {
    int t = threadIdx.x;
    int v = (t < SCAN_BLOCKS) ? g_bsum[t] : 0;
    int lane = t & 31, w = t >> 5;
    int x = v;
#pragma unroll
    for (int o = 1; o < 32; o <<= 1) {
        int y = __shfl_up_sync(0xffffffffu, x, o);
        if (lane >= o) x += y;
    }
    __shared__ int wsum[8];
    if (lane == 31) wsum[w] = x;
    __syncthreads();
    if (w == 0) {
        int s = (lane < 8) ? wsum[lane] : 0;
#pragma unroll
        for (int o = 1; o < 8; o <<= 1) {
            int y = __shfl_up_sync(0xffffffffu, s, o);
            if (lane >= o) s += y;
        }
        if (lane < 8) wsum[lane] = s;
    }
    __syncthreads();
    int incl = x + (w > 0 ? wsum[w - 1] : 0);
    if (t < SCAN_BLOCKS) g_bsum[t] = incl - v;
}
__global__ void k_scan3() {
    int t = threadIdx.x, b = blockIdx.x;
    int i = b * 256 + t;
    if (i < Nn) {
        int off = g_off[i] + g_bsum[b];
        g_off[i] = off;
        g_cursor[i] = off;
    }
    if (i == 0) g_off[Nn] = Ee;
}
__global__ void k_scatter(const int* __restrict__ row, const int* __restrict__ col) {
    int e = blockIdx.x * blockDim.x + threadIdx.x;
    if (e < Ee) {
        int d = row[e];
        int s = col[e];
        int pos = atomicAdd(&g_cursor[d], 1);
        float nm = g_disqrt[d] * g_disqrt[s];
        g_edge[pos] = make_int2(s, __float_as_int(nm));
    }
}

// ---------------- all-weights bf16 split ----------------
__global__ void k_wsplit_all(const float* __restrict__ W1, const float* __restrict__ W2,
                             const float* __restrict__ W3, const float* __restrict__ Wl) {
    int idx = blockIdx.x * blockDim.x + threadIdx.x;
    const int S1 = Dd * Hh;
    const int SW = Hh * Hh;
    const int total = S1 + 3 * SW;
    if (idx >= total) return;
    const float* src;
    int dofs;
    if (idx < S1) { src = W1 + idx; dofs = idx; }
    else {
        int r = idx - S1;
        int which = r / SW, o = r % SW;
        src = (which == 0 ? W2 : which == 1 ? W3 : Wl) + o;
        dofs = (which + 1) * SW + o;
    }
    float v = *src;
    __nv_bfloat16 h = __float2bfloat16_rn(v);
    g_whi[dofs] = h;
    g_wlo[dofs] = __float2bfloat16_rn(v - __bfloat162float(h));
}

// ---------------- aggregation (warp/node, fused BN+ReLU, unroll-2, fp32/fp16 src) ----------------
template <int KC, bool BN, bool HSRC>
__global__ void k_agg(const void* __restrict__ srcv,
                      const float* __restrict__ stats_in,
                      const float* __restrict__ gamma, const float* __restrict__ beta,
                      __nv_bfloat16* __restrict__ dhi, __nv_bfloat16* __restrict__ dlo) {
    constexpr int Q = KC / 128;
    int wid = threadIdx.x >> 5, lane = threadIdx.x & 31;
    int node = blockIdx.x * 8 + wid;
    if (node >= Nn) return;

    float scale[Q][4], shift[Q][4];
    if (BN) {
        const float invN = 1.0f / (float)Nn;
#pragma unroll
        for (int q = 0; q < Q; q++)
#pragma unroll
            for (int k = 0; k < 4; k++) {
                int j = q * 128 + lane * 4 + k;
                float mu = stats_in[j] * invN;
                float var = fmaxf(stats_in[Hh + j] * invN - mu * mu, 0.0f);
                float sc = gamma[j] * rsqrtf(var + EPSV);
                scale[q][k] = sc;
                shift[q][k] = beta[j] - mu * sc;
            }
    }

    // fetch: 4 consecutive values of row r at column block (q, lane)
    auto fetch = [&](int r, int q, float t[4]) {
        if constexpr (HSRC) {
            float2 raw = ((const float2*)srcv)[(size_t)r * (KC / 4) + q * 32 + lane];
            float2 fa = __half22float2(*(__half2*)&raw.x);
            float2 fb = __half22float2(*(__half2*)&raw.y);
            t[0] = fa.x; t[1] = fa.y; t[2] = fb.x; t[3] = fb.y;
        } else {
            float4 v = ((const float4*)srcv)[(size_t)r * (KC / 4) + q * 32 + lane];
            t[0] = v.x; t[1] = v.y; t[2] = v.z; t[3] = v.w;
        }
    };

    float dsq = g_disqrt[node];
    float sl = dsq * dsq;

    float acc[Q][4];
#pragma unroll
    for (int q = 0; q < Q; q++) {
        float t[4];
        fetch(node, q, t);
#pragma unroll
        for (int k = 0; k < 4; k++) {
            float u = BN ? fmaxf(fmaf(t[k], scale[q][k], shift[q][k]), 0.0f) : t[k];
            acc[q][k] = u * sl;
        }
    }

    int e0 = g_off[node], e1 = g_off[node + 1];
    int e = e0;
    for (; e + 2 <= e1; e += 2) {
        int2 ed0 = g_edge[e];
        int2 ed1 = g_edge[e + 1];
        float nm0 = __int_as_float(ed0.y);
        float nm1 = __int_as_float(ed1.y);
        float t0[Q][4], t1[Q][4];
#pragma unroll
        for (int q = 0; q < Q; q++) {
            fetch(ed0.x, q, t0[q]);
            fetch(ed1.x, q, t1[q]);
        }
#pragma unroll
        for (int q = 0; q < Q; q++)
#pragma unroll
            for (int k = 0; k < 4; k++) {
                float u0 = BN ? fmaxf(fmaf(t0[q][k], scale[q][k], shift[q][k]), 0.0f) : t0[q][k];
                acc[q][k] = fmaf(u0, nm0, acc[q][k]);
                float u1 = BN ? fmaxf(fmaf(t1[q][k], scale[q][k], shift[q][k]), 0.0f) : t1[q][k];
                acc[q][k] = fmaf(u1, nm1, acc[q][k]);
            }
    }
    if (e < e1) {
        int2 ed = g_edge[e];
        float nm = __int_as_float(ed.y);
#pragma unroll
        for (int q = 0; q < Q; q++) {
            float t[4];
            fetch(ed.x, q, t);
#pragma unroll
            for (int k = 0; k < 4; k++) {
                float u = BN ? fmaxf(fmaf(t[k], scale[q][k], shift[q][k]), 0.0f) : t[k];
                acc[q][k] = fmaf(u, nm, acc[q][k]);
            }
        }
    }

#pragma unroll
    for (int q = 0; q < Q; q++) {
        size_t bb = (size_t)node * KC + q * 128 + lane * 4;
        float h[4], l[4];
#pragma unroll
        for (int k = 0; k < 4; k++) {
            __nv_bfloat16 hb = __float2bfloat16_rn(acc[q][k]);
            h[k] = __bfloat162float(hb);
            l[k] = acc[q][k] - h[k];
        }
        *(__nv_bfloat162*)(dhi + bb) = __floats2bfloat162_rn(h[0], h[1]);
        *(__nv_bfloat162*)(dhi + bb + 2) = __floats2bfloat162_rn(h[2], h[3]);
        *(__nv_bfloat162*)(dlo + bb) = __floats2bfloat162_rn(l[0], l[1]);
        *(__nv_bfloat162*)(dlo + bb + 2) = __floats2bfloat162_rn(l[2], l[3]);
    }
}

// ---------------- 3xBF16 wmma GEMM, 2-stage cp.async, fused stats ----------------
// HOUT: write C as fp16 (transport precision); else fp32.
#define GBK 32
#define ALD 40
#define BLD 136
#define CLD 132
#define STAGE_BYTES ((2 * 128 * ALD * 2 + 2 * GBK * BLD * 2) * 2)  // 75776
#define CTILE_BYTES (128 * CLD * 4)                                 // 67584
#define SMEM_GEMM (STAGE_BYTES > CTILE_BYTES ? STAGE_BYTES : CTILE_BYTES)

using AFrag = wmma::fragment<wmma::matrix_a, 16, 16, 16, __nv_bfloat16, wmma::row_major>;
using BFrag = wmma::fragment<wmma::matrix_b, 16, 16, 16, __nv_bfloat16, wmma::row_major>;
using CFrag = wmma::fragment<wmma::accumulator, 16, 16, 16, float>;

template <bool HOUT>
__global__ __launch_bounds__(256) void k_gemm(const __nv_bfloat16* __restrict__ Ahi,
                                              const __nv_bfloat16* __restrict__ Alo,
                                              const __nv_bfloat16* __restrict__ Bhi,
                                              const __nv_bfloat16* __restrict__ Blo,
                                              void* __restrict__ Cv,
                                              float* __restrict__ stats,
                                              int M, int K) {
    extern __shared__ __nv_bfloat16 sm[];
    __nv_bfloat16* AH = sm;
    __nv_bfloat16* AL = AH + 2 * 128 * ALD;
    __nv_bfloat16* BH = AL + 2 * 128 * ALD;
    __nv_bfloat16* BL = BH + 2 * GBK * BLD;

    const int tid = threadIdx.x;
    const int warp = tid >> 5;
    const int rowBase = blockIdx.y * 128;
    const int colBase = blockIdx.x * 128;
    const int wm = warp & 3;
    const int wn = warp >> 2;

    CFrag c[2][4];
#pragma unroll
    for (int i = 0; i < 2; i++)
#pragma unroll
        for (int j = 0; j < 4; j++) wmma::fill_fragment(c[i][j], 0.0f);

    auto load_stage = [&](int buf, int k0) {
#pragma unroll
        for (int t = 0; t < 2; t++) {
            int id = tid + t * 256;
            int r = id >> 2;
            int cc = (id & 3) * 8;
            int grow = rowBase + r;
            size_t gofs = (size_t)(grow < M ? grow : 0) * K + k0 + cc;
            int bytes = grow < M ? 16 : 0;
            cp16((uint32_t)__cvta_generic_to_shared(AH + ((size_t)buf * 128 + r) * ALD + cc),
                 Ahi + gofs, bytes);
            cp16((uint32_t)__cvta_generic_to_shared(AL + ((size_t)buf * 128 + r) * ALD + cc),
                 Alo + gofs, bytes);
        }
#pragma unroll
        for (int t = 0; t < 2; t++) {
            int id = tid + t * 256;
            int kr = id >> 4;
            int nc = (id & 15) * 8;
            size_t gofs = (size_t)(k0 + kr) * Hh + colBase + nc;
            cp16((uint32_t)__cvta_generic_to_shared(BH + ((size_t)buf * GBK + kr) * BLD + nc),
                 Bhi + gofs, 16);
            cp16((uint32_t)__cvta_generic_to_shared(BL + ((size_t)buf * GBK + kr) * BLD + nc),
                 Blo + gofs, 16);
        }
    };

    const int NC = K >> 5;
    load_stage(0, 0);
    CP_COMMIT();

    for (int cidx = 0; cidx < NC; cidx++) {
        int buf = cidx & 1;
        if (cidx + 1 < NC) {
            load_stage(buf ^ 1, (cidx + 1) << 5);
            CP_COMMIT();
            CP_WAIT1();
        } else {
            CP_WAIT0();
        }
        __syncthreads();

#pragma unroll
        for (int ks = 0; ks < 2; ks++) {
            AFrag ah[2], al[2];
            BFrag bh[4], bl[4];
#pragma unroll
            for (int i = 0; i < 2; i++) {
                const __nv_bfloat16* pa = AH + ((size_t)buf * 128 + wm * 32 + i * 16) * ALD + ks * 16;
                wmma::load_matrix_sync(ah[i], pa, ALD);
                wmma::load_matrix_sync(al[i], pa + 2 * 128 * ALD, ALD);
            }
#pragma unroll
            for (int j = 0; j < 4; j++) {
                const __nv_bfloat16* pb = BH + ((size_t)buf * GBK + ks * 16) * BLD + wn * 64 + j * 16;
                wmma::load_matrix_sync(bh[j], pb, BLD);
                wmma::load_matrix_sync(bl[j], pb + 2 * GBK * BLD, BLD);
            }
#pragma unroll
            for (int i = 0; i < 2; i++)
#pragma unroll
                for (int j = 0; j < 4; j++) {
                    wmma::mma_sync(c[i][j], ah[i], bh[j], c[i][j]);
                    wmma::mma_sync(c[i][j], ah[i], bl[j], c[i][j]);
                    wmma::mma_sync(c[i][j], al[i], bh[j], c[i][j]);
                }
        }
        __syncthreads();
    }

    if constexpr (HOUT) {
        // restage fp32 C tile in smem, then fp16 store + stats from it
        float* ct = (float*)sm;
#pragma unroll
        for (int i = 0; i < 2; i++)
#pragma unroll
            for (int j = 0; j < 4; j++)
                wmma::store_matrix_sync(ct + (size_t)(wm * 32 + i * 16) * CLD + wn * 64 + j * 16,
                                        c[i][j], CLD, wmma::mem_row_major);
        __syncthreads();
        __half* Ch = (__half*)Cv;
#pragma unroll
        for (int i = 0; i < 32; i++) {
            int idx = tid + i * 256;   // 0..8191 half2 units (128 rows x 64 pairs)
            int r = idx >> 6;
            int cp = idx & 63;
            float a = ct[(size_t)r * CLD + cp * 2];
            float b = ct[(size_t)r * CLD + cp * 2 + 1];
            ((__half2*)(Ch + (size_t)(rowBase + r) * Hh + colBase))[cp] = __floats2half2_rn(a, b);
        }
        if (stats) {
            int col = tid & 127;
            int half_ = tid >> 7;
            const float* p = ct + (size_t)half_ * 64 * CLD + col;
            float s = 0.f, s2 = 0.f;
#pragma unroll 8
            for (int r = 0; r < 64; r++) {
                float v = p[(size_t)r * CLD];
                s += v;
                s2 = fmaf(v, v, s2);
            }
            atomicAdd(&stats[colBase + col], s);
            atomicAdd(&stats[Hh + colBase + col], s2);
        }
    } else {
        float* C = (float*)Cv;
#pragma unroll
        for (int i = 0; i < 2; i++)
#pragma unroll
            for (int j = 0; j < 4; j++) {
                int grow = rowBase + wm * 32 + i * 16;
                wmma::store_matrix_sync(C + (size_t)grow * Hh + colBase + wn * 64 + j * 16,
                                        c[i][j], Hh, wmma::mem_row_major);
            }
    }
}

// ---------------- head: gather + BN3 + relu + bf16 split (fp16 source) ----------------
__global__ void k_gather_bn(const int* __restrict__ train, const float* __restrict__ stats,
                            const float* __restrict__ gamma, const float* __restrict__ beta) {
    int idx = blockIdx.x * blockDim.x + threadIdx.x;
    if (idx >= Tt * 64) return;
    int t = idx >> 6, cq = idx & 63;
    int node = train[t];
    float2 raw = ((const float2*)g_hw)[(size_t)node * 64 + cq];
    float2 fa = __half22float2(*(__half2*)&raw.x);
    float2 fb = __half22float2(*(__half2*)&raw.y);
    float tv[4] = {fa.x, fa.y, fb.x, fb.y};
    const float invN = 1.0f / (float)Nn;
    float h[4], l[4];
#pragma unroll
    for (int k = 0; k < 4; k++) {
        int j = cq * 4 + k;
        float mu = stats[j] * invN;
        float var = fmaxf(stats[Hh + j] * invN - mu * mu, 0.0f);
        float sc = gamma[j] * rsqrtf(var + EPSV);
        float u = fmaxf(fmaf(tv[k], sc, beta[j] - mu * sc), 0.0f);
        __nv_bfloat16 hb = __float2bfloat16_rn(u);
        h[k] = __bfloat162float(hb);
        l[k] = u - h[k];
    }
    size_t base = (size_t)t * Hh + cq * 4;
    *(__nv_bfloat162*)(g_ghi + base) = __floats2bfloat162_rn(h[0], h[1]);
    *(__nv_bfloat162*)(g_ghi + base + 2) = __floats2bfloat162_rn(h[2], h[3]);
    *(__nv_bfloat162*)(g_glo + base) = __floats2bfloat162_rn(l[0], l[1]);
    *(__nv_bfloat162*)(g_glo + base + 2) = __floats2bfloat162_rn(l[2], l[3]);
}

__global__ void k_out(const float* __restrict__ bl, const float* __restrict__ Wf,
                      const float* __restrict__ bf, float* __restrict__ out) {
    int warp = (blockIdx.x * blockDim.x + threadIdx.x) >> 5;
    int lane = threadIdx.x & 31;
    if (warp >= Tt) return;
    float acc = 0.f;
    const float* hp = g_ho + (size_t)warp * Hh;
#pragma unroll
    for (int j0 = 0; j0 < Hh; j0 += 32) {
        int j = j0 + lane;
        float v = fmaxf(hp[j] + bl[j], 0.0f);
        acc = fmaf(v, Wf[j], acc);
    }
#pragma unroll
    for (int o = 16; o > 0; o >>= 1) acc += __shfl_xor_sync(0xffffffffu, acc, o);
    if (lane == 0) out[warp] = acc + bf[0];
}

// ---------------- launch ----------------
extern "C" void kernel_launch(void* const* d_in, const int* in_sizes, int n_in,
                              void* d_out, int out_size) {
    const float* x = (const float*)d_in[0];
    const int* ei = (const int*)d_in[1];
    const int* train = (const int*)d_in[2];
    const float* W1 = (const float*)d_in[3];
    const float* W2 = (const float*)d_in[5];
    const float* W3 = (const float*)d_in[7];
    const float* g1 = (const float*)d_in[9];
    const float* be1 = (const float*)d_in[10];
    const float* g2 = (const float*)d_in[11];
    const float* be2 = (const float*)d_in[12];
    const float* g3 = (const float*)d_in[13];
    const float* be3 = (const float*)d_in[14];
    const float* Wl = (const float*)d_in[15];
    const float* bl = (const float*)d_in[16];
    const float* Wf = (const float*)d_in[17];
    const float* bf = (const float*)d_in[18];
    float* out = (float*)d_out;

    const int* row = ei;
    const int* col = ei + Ee;

    float *p_ho, *p_stats;
    __half* p_hw;
    __nv_bfloat16 *p_ahi, *p_alo, *p_ghi, *p_glo, *p_whi, *p_wlo;
    cudaGetSymbolAddress((void**)&p_hw, g_hw);
    cudaGetSymbolAddress((void**)&p_ho, g_ho);
    cudaGetSymbolAddress((void**)&p_stats, g_stats4);
    cudaGetSymbolAddress((void**)&p_ahi, g_ahi);
    cudaGetSymbolAddress((void**)&p_alo, g_alo);
    cudaGetSymbolAddress((void**)&p_ghi, g_ghi);
    cudaGetSymbolAddress((void**)&p_glo, g_glo);
    cudaGetSymbolAddress((void**)&p_whi, g_whi);
    cudaGetSymbolAddress((void**)&p_wlo, g_wlo);

    cudaFuncSetAttribute(k_gemm<true>, cudaFuncAttributeMaxDynamicSharedMemorySize, SMEM_GEMM);
    cudaFuncSetAttribute(k_gemm<false>, cudaFuncAttributeMaxDynamicSharedMemorySize, SMEM_GEMM);

    // ---- graph preprocessing ----
    k_zero_init<<<(Nn + 255) / 256, 256>>>();
    k_count<<<(Ee + 255) / 256, 256>>>(row);
    k_scan1<<<SCAN_BLOCKS, 256>>>();
    k_scan2<<<1, 256>>>();
    k_scan3<<<SCAN_BLOCKS, 256>>>();
    k_scatter<<<(Ee + 255) / 256, 256>>>(row, col);
    k_wsplit_all<<<(Dd * Hh + 3 * Hh * Hh + 255) / 256, 256>>>(W1, W2, W3, Wl);

    const int AGG_B = (Nn + 7) / 8;   // 6250
    dim3 gemm_grid(2, NPAD / 128);
    dim3 head_grid(2, TPAD / 128);
    float* st0 = p_stats + 0 * 2 * Hh;
    float* st1 = p_stats + 1 * 2 * Hh;
    float* st2 = p_stats + 2 * 2 * Hh;

    // ---- layer 1: agg(x fp32) -> bf16; GEMM K=128 -> fp16 hw ----
    k_agg<128, false, false><<<AGG_B, 256>>>(x, nullptr, nullptr, nullptr, p_ahi, p_alo);
    k_gemm<true><<<gemm_grid, 256, SMEM_GEMM>>>(p_ahi, p_alo, p_whi, p_wlo, p_hw, st0, Nn, Dd);

    // ---- layer 2: agg(bn1+relu(hw fp16)) -> bf16; GEMM -> fp16 hw ----
    k_agg<256, true, true><<<AGG_B, 256>>>(p_hw, st0, g1, be1, p_ahi, p_alo);
    k_gemm<true><<<gemm_grid, 256, SMEM_GEMM>>>(p_ahi, p_alo, p_whi + 1 * Hh * Hh,
                                                p_wlo + 1 * Hh * Hh, p_hw, st1, Nn, Hh);

    // ---- layer 3 ----
    k_agg<256, true, true><<<AGG_B, 256>>>(p_hw, st1, g2, be2, p_ahi, p_alo);
    k_gemm<true><<<gemm_grid, 256, SMEM_GEMM>>>(p_ahi, p_alo, p_whi + 2 * Hh * Hh,
                                                p_wlo + 2 * Hh * Hh, p_hw, st2, Nn, Hh);

    // ---- head: gather+bn3 (fp16 src) -> bf16; Wl GEMM -> fp32 ho; fused relu+Wf dot ----
    k_gather_bn<<<(Tt * 64 + 255) / 256, 256>>>(train, st2, g3, be3);
    k_gemm<false><<<head_grid, 256, SMEM_GEMM>>>(p_ghi, p_glo, p_whi + 3 * Hh * Hh,
                                                 p_wlo + 3 * Hh * Hh, p_ho, nullptr, Tt, Hh);
    k_out<<<(Tt * 32 + 255) / 256, 256>>>(bl, Wf, bf, out);
}